// round 1
// baseline (speedup 1.0000x reference)
#include <cuda_runtime.h>
#include <cuda_bf16.h>
#include <math.h>

// Problem constants
#define BB   32
#define INF  128
#define HH   1024
#define OUTF 128
#define KCAT (INF + HH)   // 1152

// Scratch (allocation-free rule: __device__ globals)
__device__ float g_combined[BB * KCAT];
__device__ float g_c0[BB * HH];
__device__ float g_c1[BB * HH];
__device__ float g_c2[BB * HH];
__device__ float g_logits[BB * OUTF];

// Build combined = cat(x, hidden)
__global__ void build_combined_kernel(const float* __restrict__ x,
                                      const float* __restrict__ hidden) {
    int tid = blockIdx.x * blockDim.x + threadIdx.x;
    if (tid >= BB * KCAT) return;
    int b = tid / KCAT;
    int c = tid % KCAT;
    g_combined[tid] = (c < INF) ? x[b * INF + c] : hidden[b * HH + (c - INF)];
}

// Batched matvec + optional tanh. One warp per output row.
// W is [B, Hout, K] row-major; row index = global warp id = b*Hout + o.
template <int K, bool DO_TANH>
__global__ void matvec_kernel(const float* __restrict__ W,
                              const float* __restrict__ bias,
                              const float* __restrict__ in,
                              float* __restrict__ out,
                              int Hout) {
    const int warp = (blockIdx.x * blockDim.x + threadIdx.x) >> 5;
    const int lane = threadIdx.x & 31;
    const int total = BB * Hout;
    if (warp >= total) return;
    const int b = warp / Hout;
    const int o = warp - b * Hout;

    const float4* __restrict__ Wr = reinterpret_cast<const float4*>(W + (size_t)warp * K);
    const float4* __restrict__ xr = reinterpret_cast<const float4*>(in + (size_t)b * K);

    float sum = 0.f;
    constexpr int NIT = K / 128;   // float4s per lane
#pragma unroll
    for (int j = 0; j < NIT; j++) {
        float4 w = Wr[j * 32 + lane];
        float4 v = xr[j * 32 + lane];
        sum += w.x * v.x + w.y * v.y + w.z * v.z + w.w * v.w;
    }
#pragma unroll
    for (int off = 16; off; off >>= 1)
        sum += __shfl_xor_sync(0xFFFFFFFFu, sum, off);

    if (lane == 0) {
        float r = sum + bias[o];
        out[warp] = DO_TANH ? tanhf(r) : r;
    }
}

// Fused heads: rows [0, B*H) -> Wh (tanh -> new_hidden), rows [B*H, B*H+B*OUT) -> Wo (logits)
__global__ void heads_kernel(const float* __restrict__ Wh, const float* __restrict__ bh,
                             const float* __restrict__ Wo, const float* __restrict__ bo,
                             float* __restrict__ new_hidden_out) {
    const int warp = (blockIdx.x * blockDim.x + threadIdx.x) >> 5;
    const int lane = threadIdx.x & 31;
    const int ROWS_H = BB * HH;
    const int ROWS_O = BB * OUTF;
    if (warp >= ROWS_H + ROWS_O) return;

    const bool is_h = (warp < ROWS_H);
    int row, b, o;
    const float* Wbase;
    if (is_h) { row = warp; b = row / HH; o = row - b * HH; Wbase = Wh; }
    else      { row = warp - ROWS_H; b = row / OUTF; o = row - b * OUTF; Wbase = Wo; }

    const float4* __restrict__ Wr = reinterpret_cast<const float4*>(Wbase + (size_t)row * HH);
    const float4* __restrict__ xr = reinterpret_cast<const float4*>(g_c2 + (size_t)b * HH);

    float sum = 0.f;
#pragma unroll
    for (int j = 0; j < HH / 128; j++) {
        float4 w = Wr[j * 32 + lane];
        float4 v = xr[j * 32 + lane];
        sum += w.x * v.x + w.y * v.y + w.z * v.z + w.w * v.w;
    }
#pragma unroll
    for (int off = 16; off; off >>= 1)
        sum += __shfl_xor_sync(0xFFFFFFFFu, sum, off);

    if (lane == 0) {
        if (is_h) new_hidden_out[row] = tanhf(sum + bh[o]);
        else      g_logits[row] = sum + bo[o];
    }
}

// log_softmax over 128 logits per batch; one warp per batch row (4 values/lane).
__global__ void log_softmax_kernel(float* __restrict__ out) {
    const int warp = threadIdx.x >> 5;   // 0..31 (single block of 1024)
    const int lane = threadIdx.x & 31;
    const float* l = g_logits + warp * OUTF;

    float v[4];
#pragma unroll
    for (int i = 0; i < 4; i++) v[i] = l[i * 32 + lane];

    float m = fmaxf(fmaxf(v[0], v[1]), fmaxf(v[2], v[3]));
#pragma unroll
    for (int off = 16; off; off >>= 1)
        m = fmaxf(m, __shfl_xor_sync(0xFFFFFFFFu, m, off));

    float s = 0.f;
#pragma unroll
    for (int i = 0; i < 4; i++) s += __expf(v[i] - m);
#pragma unroll
    for (int off = 16; off; off >>= 1)
        s += __shfl_xor_sync(0xFFFFFFFFu, s, off);

    float lse = m + logf(s);
#pragma unroll
    for (int i = 0; i < 4; i++)
        out[warp * OUTF + i * 32 + lane] = v[i] - lse;
}

extern "C" void kernel_launch(void* const* d_in, const int* in_sizes, int n_in,
                              void* d_out, int out_size) {
    const float* x      = (const float*)d_in[0];
    const float* hidden = (const float*)d_in[1];
    const float* W0 = (const float*)d_in[2];
    const float* b0 = (const float*)d_in[3];
    const float* W1 = (const float*)d_in[4];
    const float* b1 = (const float*)d_in[5];
    const float* W2 = (const float*)d_in[6];
    const float* b2 = (const float*)d_in[7];
    const float* Wh = (const float*)d_in[8];
    const float* bh = (const float*)d_in[9];
    const float* Wo = (const float*)d_in[10];
    const float* bo = (const float*)d_in[11];

    float* out = (float*)d_out;                 // [B*OUT] log_softmax output
    float* new_hidden = out + BB * OUTF;        // then [B*H] new_hidden

    float *c0, *c1, *c2, *comb;
    cudaGetSymbolAddress((void**)&comb, g_combined);
    cudaGetSymbolAddress((void**)&c0, g_c0);
    cudaGetSymbolAddress((void**)&c1, g_c1);
    cudaGetSymbolAddress((void**)&c2, g_c2);

    // 1) combined = cat(x, hidden)
    build_combined_kernel<<<(BB * KCAT + 255) / 256, 256>>>(x, hidden);

    // 2) three hidden layers (warp per row, 8 warps/block)
    const int TPB = 256;
    int rowsH = BB * HH;                        // 32768 warps
    int blocksH = (rowsH * 32 + TPB - 1) / TPB; // 4096
    matvec_kernel<KCAT, true><<<blocksH, TPB>>>(W0, b0, comb, c0, HH);
    matvec_kernel<HH,   true><<<blocksH, TPB>>>(W1, b1, c0,   c1, HH);
    matvec_kernel<HH,   true><<<blocksH, TPB>>>(W2, b2, c1,   c2, HH);

    // 3) fused Wh (tanh -> new_hidden) + Wo (logits)
    int rowsHeads = BB * HH + BB * OUTF;        // 36864 warps
    int blocksHeads = (rowsHeads * 32 + TPB - 1) / TPB;
    heads_kernel<<<blocksHeads, TPB>>>(Wh, bh, Wo, bo, new_hidden);

    // 4) log_softmax epilogue (one warp per batch row)
    log_softmax_kernel<<<1, BB * 32>>>(out);

    (void)in_sizes; (void)n_in; (void)out_size;
}

// round 2
// speedup vs baseline: 1.0851x; 1.0851x over previous
#include <cuda_runtime.h>
#include <cuda_bf16.h>
#include <math.h>

// Problem constants
#define BB   32
#define INF  128
#define HH   1024
#define OUTF 128
#define KCAT (INF + HH)   // 1152
#define TPB  256
#define RPB  8            // rows (warps) per block

// Scratch (allocation-free rule: __device__ globals)
__device__ float g_c0[BB * HH];
__device__ float g_c1[BB * HH];
__device__ float g_c2[BB * HH];
__device__ float g_logits[BB * OUTF];

// Batched matvec + tanh. 8 warps/block = 8 consecutive rows of the SAME batch.
// Activation vector staged in shared memory once per block; W streamed with __ldcs,
// all NIT LDG.128s front-batched into registers for max per-warp MLP.
// LAYER0: builds combined = cat(x[b], hidden[b]) in the smem stage.
template <int K, bool LAYER0>
__global__ __launch_bounds__(TPB) void matvec_kernel(
    const float* __restrict__ W, const float* __restrict__ bias,
    const float* __restrict__ in0,   // LAYER0: x ; else: activations [B,K]
    const float* __restrict__ in1,   // LAYER0: hidden ; else unused
    float* __restrict__ out, int Hout)
{
    __shared__ float4 xs[K / 4];

    const int rowbase = blockIdx.x * RPB;
    const int b = rowbase / Hout;

    // Stage activation vector for this batch into smem (block-cooperative).
    if (LAYER0) {
        const float4* xv = reinterpret_cast<const float4*>(in0 + (size_t)b * INF);
        const float4* hv = reinterpret_cast<const float4*>(in1 + (size_t)b * HH);
#pragma unroll
        for (int i = threadIdx.x; i < K / 4; i += TPB)
            xs[i] = (i < INF / 4) ? xv[i] : hv[i - INF / 4];
    } else {
        const float4* src = reinterpret_cast<const float4*>(in0 + (size_t)b * K);
#pragma unroll
        for (int i = threadIdx.x; i < K / 4; i += TPB)
            xs[i] = src[i];
    }
    __syncthreads();

    const int warp = threadIdx.x >> 5;
    const int lane = threadIdx.x & 31;
    const int row  = rowbase + warp;
    const int o    = row - b * Hout;

    const float4* __restrict__ Wr = reinterpret_cast<const float4*>(W + (size_t)row * K);
    constexpr int NIT = K / 128;

    // Front-batch all W loads (streaming hint — no reuse, don't thrash L2).
    float4 w[NIT];
#pragma unroll
    for (int j = 0; j < NIT; j++)
        w[j] = __ldcs(Wr + j * 32 + lane);

    float sum = 0.f;
#pragma unroll
    for (int j = 0; j < NIT; j++) {
        float4 v = xs[j * 32 + lane];
        sum += w[j].x * v.x + w[j].y * v.y + w[j].z * v.z + w[j].w * v.w;
    }
#pragma unroll
    for (int off = 16; off; off >>= 1)
        sum += __shfl_xor_sync(0xFFFFFFFFu, sum, off);

    if (lane == 0)
        out[row] = tanhf(sum + bias[o]);
}

// Fused heads: first NBH blocks -> Wh (tanh -> new_hidden), rest -> Wo (logits, no tanh).
__global__ __launch_bounds__(TPB) void heads_kernel(
    const float* __restrict__ Wh, const float* __restrict__ bh,
    const float* __restrict__ Wo, const float* __restrict__ bo,
    float* __restrict__ new_hidden_out)
{
    __shared__ float4 xs[HH / 4];

    const int NBH = (BB * HH) / RPB;   // 4096 blocks for Wh
    const bool is_h = (blockIdx.x < NBH);
    int rowbase, b, Hout;
    const float* Wbase; const float* bias;
    if (is_h) { rowbase = blockIdx.x * RPB;          Hout = HH;   Wbase = Wh; bias = bh; }
    else      { rowbase = (blockIdx.x - NBH) * RPB;  Hout = OUTF; Wbase = Wo; bias = bo; }
    b = rowbase / Hout;

    {
        const float4* src = reinterpret_cast<const float4*>(g_c2 + (size_t)b * HH);
#pragma unroll
        for (int i = threadIdx.x; i < HH / 4; i += TPB)
            xs[i] = src[i];
    }
    __syncthreads();

    const int warp = threadIdx.x >> 5;
    const int lane = threadIdx.x & 31;
    const int row  = rowbase + warp;
    const int o    = row - b * Hout;

    const float4* __restrict__ Wr = reinterpret_cast<const float4*>(Wbase + (size_t)row * HH);
    constexpr int NIT = HH / 128;

    float4 w[NIT];
#pragma unroll
    for (int j = 0; j < NIT; j++)
        w[j] = __ldcs(Wr + j * 32 + lane);

    float sum = 0.f;
#pragma unroll
    for (int j = 0; j < NIT; j++) {
        float4 v = xs[j * 32 + lane];
        sum += w[j].x * v.x + w[j].y * v.y + w[j].z * v.z + w[j].w * v.w;
    }
#pragma unroll
    for (int off = 16; off; off >>= 1)
        sum += __shfl_xor_sync(0xFFFFFFFFu, sum, off);

    if (lane == 0) {
        if (is_h) new_hidden_out[row] = tanhf(sum + bias[o]);
        else      g_logits[row] = sum + bias[o];
    }
}

// log_softmax over 128 logits per batch; one warp per batch row (4 values/lane).
__global__ void log_softmax_kernel(float* __restrict__ out) {
    const int warp = threadIdx.x >> 5;   // 0..31 (single block of 1024)
    const int lane = threadIdx.x & 31;
    const float* l = g_logits + warp * OUTF;

    float v[4];
#pragma unroll
    for (int i = 0; i < 4; i++) v[i] = l[i * 32 + lane];

    float m = fmaxf(fmaxf(v[0], v[1]), fmaxf(v[2], v[3]));
#pragma unroll
    for (int off = 16; off; off >>= 1)
        m = fmaxf(m, __shfl_xor_sync(0xFFFFFFFFu, m, off));

    float s = 0.f;
#pragma unroll
    for (int i = 0; i < 4; i++) s += __expf(v[i] - m);
#pragma unroll
    for (int off = 16; off; off >>= 1)
        s += __shfl_xor_sync(0xFFFFFFFFu, s, off);

    float lse = m + logf(s);
#pragma unroll
    for (int i = 0; i < 4; i++)
        out[warp * OUTF + i * 32 + lane] = v[i] - lse;
}

extern "C" void kernel_launch(void* const* d_in, const int* in_sizes, int n_in,
                              void* d_out, int out_size) {
    const float* x      = (const float*)d_in[0];
    const float* hidden = (const float*)d_in[1];
    const float* W0 = (const float*)d_in[2];
    const float* b0 = (const float*)d_in[3];
    const float* W1 = (const float*)d_in[4];
    const float* b1 = (const float*)d_in[5];
    const float* W2 = (const float*)d_in[6];
    const float* b2 = (const float*)d_in[7];
    const float* Wh = (const float*)d_in[8];
    const float* bh = (const float*)d_in[9];
    const float* Wo = (const float*)d_in[10];
    const float* bo = (const float*)d_in[11];

    float* out = (float*)d_out;                 // [B*OUT] log_softmax output
    float* new_hidden = out + BB * OUTF;        // then [B*H] new_hidden

    float *c0, *c1, *c2;
    cudaGetSymbolAddress((void**)&c0, g_c0);
    cudaGetSymbolAddress((void**)&c1, g_c1);
    cudaGetSymbolAddress((void**)&c2, g_c2);

    const int blocksH = (BB * HH) / RPB;        // 4096
    // Layer 0 (fused concat) + layers 1,2
    matvec_kernel<KCAT, true ><<<blocksH, TPB>>>(W0, b0, x,  hidden, c0, HH);
    matvec_kernel<HH,   false><<<blocksH, TPB>>>(W1, b1, c0, nullptr, c1, HH);
    matvec_kernel<HH,   false><<<blocksH, TPB>>>(W2, b2, c1, nullptr, c2, HH);

    // Fused Wh (tanh -> new_hidden) + Wo (logits)
    const int blocksHeads = (BB * HH) / RPB + (BB * OUTF) / RPB;  // 4608
    heads_kernel<<<blocksHeads, TPB>>>(Wh, bh, Wo, bo, new_hidden);

    // log_softmax epilogue (one warp per batch row)
    log_softmax_kernel<<<1, BB * 32>>>(out);

    (void)in_sizes; (void)n_in; (void)out_size;
}